// round 15
// baseline (speedup 1.0000x reference)
#include <cuda_runtime.h>
#include <cstdint>
#include <math.h>

#define N 4096
#define DIN 64
#define DOUT 64
#define NEG_HUGE (-3.402823466e38f)

// ---- scratch (device globals; no runtime allocation) ----
__device__ __align__(16) float g_P[(size_t)N * N];     // 64 MB: final P
// A operand, [k][m'] with m-pairs (m, m+8) adjacent within 16-blocks
__device__ __align__(16) float g_AtcP[(size_t)N * N];  // also topk scratch later
// B operand, k-folded: phys row = (k>>3)*4 + (k&3), col = 2n + ((k>>2)&1)
__device__ __align__(16) float g_BtP[(size_t)N * N];   // (N/2) rows x 2N cols
__device__ __align__(16) float g_dinv[N];
__device__ __align__(16) float g_c[N];
__device__ __align__(16) float g_e[N];
__device__ float g_t[2];

// ===========================================================================
// helpers
// ===========================================================================
__device__ __forceinline__ uint32_t smem_u32(const void* p) {
    uint32_t a;
    asm("{ .reg .u64 t; cvta.to.shared.u64 t, %1; cvt.u32.u64 %0, t; }"
        : "=r"(a) : "l"(p));
    return a;
}
__device__ __forceinline__ float f2tf32(float x) {
    float y;
    asm("cvt.rna.tf32.f32 %0, %1;" : "=f"(y) : "f"(x));
    return y;
}
#define CP_ASYNC16(smem, gptr) \
    asm volatile("cp.async.cg.shared.global [%0], [%1], 16;" \
                 :: "r"(smem), "l"(gptr) : "memory")
#define CP_COMMIT() asm volatile("cp.async.commit_group;" ::: "memory")
#define CP_WAIT(n)  asm volatile("cp.async.wait_group %0;" :: "n"(n) : "memory")

__device__ __forceinline__ void mma_tf32(float* d, float2 a01, float2 a23,
                                         float2 b01) {
    asm volatile(
        "mma.sync.aligned.m16n8k8.row.col.f32.tf32.tf32.f32 "
        "{%0,%1,%2,%3}, {%4,%5,%6,%7}, {%8,%9}, {%0,%1,%2,%3};"
        : "+f"(d[0]), "+f"(d[1]), "+f"(d[2]), "+f"(d[3])
        : "r"(__float_as_uint(a01.x)), "r"(__float_as_uint(a01.y)),
          "r"(__float_as_uint(a23.x)), "r"(__float_as_uint(a23.y)),
          "r"(__float_as_uint(b01.x)), "r"(__float_as_uint(b01.y)));
}

// ===========================================================================
// Kernel 1: row sums of A -> dinv, c ; sigmoid(theta)
// ===========================================================================
__global__ __launch_bounds__(256) void k_rowsum_A(const float* __restrict__ A,
                                                  const float* __restrict__ theta) {
    int row = blockIdx.x;
    const float4* a4 = (const float4*)(A + (size_t)row * N);
    float s = 0.f;
    for (int i = threadIdx.x; i < N / 4; i += 256) {
        float4 v = a4[i];
        s += v.x + v.y + v.z + v.w;
    }
    __shared__ float red[256];
    red[threadIdx.x] = s;
    __syncthreads();
    for (int o = 128; o > 0; o >>= 1) {
        if (threadIdx.x < o) red[threadIdx.x] += red[threadIdx.x + o];
        __syncthreads();
    }
    if (threadIdx.x == 0) {
        float d = red[0];
        g_dinv[row] = rsqrtf(d);
        g_c[row] = 1.0f / d;
        if (row == 0) {
            g_t[0] = 1.0f / (1.0f + expf(-theta[0]));
            g_t[1] = 1.0f / (1.0f + expf(-theta[1]));
        }
    }
}

// ===========================================================================
// Kernel 2: prep with pair-contiguous layouts (R9-proven).
// ===========================================================================
__global__ __launch_bounds__(256) void k_prep(const float* __restrict__ A) {
    __shared__ float ta[32][33];
    __shared__ float tb[32][33];
    int tx = threadIdx.x, ty = threadIdx.y;
    int x0 = blockIdx.x * 32, y0 = blockIdx.y * 32;
    float cc = g_c[x0 + tx];
#pragma unroll
    for (int r = 0; r < 4; r++) {
        int row = y0 + ty + r * 8;
        float v = A[(size_t)row * N + x0 + tx];
        tb[ty + r * 8][tx] = f2tf32(v);
        ta[ty + r * 8][tx] = f2tf32(v * cc);
    }
    __syncthreads();
#pragma unroll
    for (int rr = 0; rr < 2; rr++) {
        int p = ty + rr * 8;
        int i = 8 * (p >> 2) + (p & 3);
        float2 val = make_float2(tb[i][tx], tb[i + 4][tx]);
        *(float2*)(g_BtP + (size_t)(y0 / 2 + p) * (2 * N) + 2 * (x0 + tx)) = val;
    }
#pragma unroll
    for (int rr = 0; rr < 2; rr++) {
        int j = 2 * (ty + 8 * rr) + (tx >> 4);
        int q = tx & 15;
        int i = 16 * (q >> 3) + (q & 7);
        int col = y0 + 16 * (q >> 3) + 2 * (q & 7);
        float2 val = make_float2(ta[i][j], ta[i + 8][j]);
        *(float2*)(g_AtcP + (size_t)(x0 + j) * N + col) = val;
    }
}

// ===========================================================================
// dummy no-op: keeps ncu's captured launch index on the GEMM
// ===========================================================================
__global__ void k_nop() {}

// ===========================================================================
// Kernel 3: tf32 mma.sync GEMM — CTA 128x128, 8 warps 4m x 2n, warp 32x64,
// LDS.64 pair-fragment loads, **3-stage cp.async pipeline with STATIC buffer
// indices** (42 groups x 3 unrolled bodies + 2-chunk tail; one barrier per
// chunk; staging precedes compute).  g_P = dinv_i*dinv_j*(t0*A + t1*M) + I
// ===========================================================================
#define BK 32
#define NCH (N / BK)             // 128
#define PITCHA 136
#define PITCHB 264
#define TILEA_F (BK * PITCHA)
#define TILEB_F ((BK / 2) * PITCHB)
#define STAGE_F (TILEA_F + TILEB_F)      // 8576 floats
#define SMEM_BYTES (3 * STAGE_F * 4)     // 102912

__device__ __forceinline__ void stage_chunk(uint32_t sbase, int buf, int ch,
                                            int i0, int j0, int tid) {
    int k0 = ch * BK;
    uint32_t sa = sbase + buf * (STAGE_F * 4);
    uint32_t sb = sa + TILEA_F * 4;
#pragma unroll
    for (int t = 0; t < 4; t++) {
        int id = tid + t * 256;
        int k = id >> 5, seg = id & 31;
        CP_ASYNC16(sa + k * (PITCHA * 4) + seg * 16,
                   g_AtcP + (size_t)(k0 + k) * N + i0 + seg * 4);
    }
#pragma unroll
    for (int t = 0; t < 4; t++) {
        int id = tid + t * 256;
        int r = id >> 6, seg = id & 63;
        CP_ASYNC16(sb + r * (PITCHB * 4) + seg * 16,
                   g_BtP + (size_t)(k0 / 2 + r) * (2 * N) + 2 * j0 + seg * 4);
    }
}

template <int RBUF>
__device__ __forceinline__ void chunk_compute(const float* sm,
                                              float (&acc)[2][8][4],
                                              int wm0, int wn0, int g, int tig) {
    const float* As = sm + RBUF * STAGE_F;
    const float* Bs = As + TILEA_F;
#pragma unroll
    for (int s = 0; s < 4; s++) {
        float2 a01[2], a23[2];
#pragma unroll
        for (int mt = 0; mt < 2; mt++) {
            int col = wm0 + 16 * mt + 2 * g;
            a01[mt] = *(const float2*)(As + (8 * s + tig) * PITCHA + col);
            a23[mt] = *(const float2*)(As + (8 * s + tig + 4) * PITCHA + col);
        }
#pragma unroll
        for (int j = 0; j < 8; j++) {
            float2 b01 = *(const float2*)(Bs + (4 * s + tig) * PITCHB +
                                          2 * (wn0 + 8 * j + g));
            mma_tf32(acc[0][j], a01[0], a23[0], b01);
            mma_tf32(acc[1][j], a01[1], a23[1], b01);
        }
    }
}

__global__ __launch_bounds__(256, 2) void k_gemm_mma(const float* __restrict__ A) {
    extern __shared__ float sm[];
    uint32_t sbase = smem_u32(sm);
    int tid = threadIdx.x;
    int wid = tid >> 5, lane = tid & 31;
    int g = lane >> 2, tig = lane & 3;
    int wm0 = (wid & 3) * 32, wn0 = (wid >> 2) * 64;
    int i0 = blockIdx.y * 128, j0 = blockIdx.x * 128;

    float acc[2][8][4];
#pragma unroll
    for (int mt = 0; mt < 2; mt++)
#pragma unroll
        for (int j = 0; j < 8; j++)
#pragma unroll
            for (int c = 0; c < 4; c++) acc[mt][j][c] = 0.f;

    // prologue: stage chunks 0 and 1 into buffers 0 and 1
    stage_chunk(sbase, 0, 0, i0, j0, tid);
    CP_COMMIT();
    stage_chunk(sbase, 1, 1, i0, j0, tid);
    CP_COMMIT();

    // main loop: 42 groups of 3 chunks with static buffer indices.
    // iter ch: wait chunk ch; sync (all warps done with buf[(ch+2)%3]'s old
    // data = chunk ch-1); stage ch+2 -> buf[(ch+2)%3]; compute buf[ch%3].
    for (int ch = 0; ch < NCH - 2; ch += 3) {
        CP_WAIT(1);
        __syncthreads();
        stage_chunk(sbase, 2, ch + 2, i0, j0, tid);
        CP_COMMIT();
        chunk_compute<0>(sm, acc, wm0, wn0, g, tig);

        CP_WAIT(1);
        __syncthreads();
        stage_chunk(sbase, 0, ch + 3, i0, j0, tid);
        CP_COMMIT();
        chunk_compute<1>(sm, acc, wm0, wn0, g, tig);

        CP_WAIT(1);
        __syncthreads();
        stage_chunk(sbase, 1, ch + 4, i0, j0, tid);
        CP_COMMIT();
        chunk_compute<2>(sm, acc, wm0, wn0, g, tig);
    }
    // tail: chunks 126 (buf 0) and 127 (buf 1); nothing left to stage
    CP_WAIT(1);
    __syncthreads();
    chunk_compute<0>(sm, acc, wm0, wn0, g, tig);
    CP_WAIT(0);
    __syncthreads();
    chunk_compute<1>(sm, acc, wm0, wn0, g, tig);
    __syncthreads();   // all reads done before epilogue reuses smem

    // ---- epilogue: t1*M scale + diag via smem transpose; t0*A term added
    //      in the coalesced store phase ----
    float t1 = g_t[1];
    float t0 = g_t[0];
    float* scr = sm;
#pragma unroll
    for (int mt = 0; mt < 2; mt++) {
        int m0 = wm0 + 16 * mt + g;
        int gi0 = i0 + m0, gi1 = gi0 + 8;
        float di0 = t1 * g_dinv[gi0];
        float di1 = t1 * g_dinv[gi1];
#pragma unroll
        for (int j = 0; j < 8; j++) {
            int n = wn0 + 8 * j + 2 * tig;
            int gj = j0 + n;
            float dj0 = g_dinv[gj], dj1 = g_dinv[gj + 1];
            float p00 = acc[mt][j][0] * di0 * dj0;
            float p01 = acc[mt][j][1] * di0 * dj1;
            float p10 = acc[mt][j][2] * di1 * dj0;
            float p11 = acc[mt][j][3] * di1 * dj1;
            if (gi0 == gj) p00 += 1.0f;
            if (gi0 == gj + 1) p01 += 1.0f;
            if (gi1 == gj) p10 += 1.0f;
            if (gi1 == gj + 1) p11 += 1.0f;
            *(float2*)(scr + m0 * 132 + n) = make_float2(p00, p01);
            *(float2*)(scr + (m0 + 8) * 132 + n) = make_float2(p10, p11);
        }
    }
    __syncthreads();
#pragma unroll
    for (int t = 0; t < 16; t++) {
        int id = tid + t * 256;
        int row = id >> 5, cg = id & 31;
        int gi = i0 + row;
        float di = t0 * g_dinv[gi];
        float4 v = *(float4*)(scr + row * 132 + cg * 4);
        float4 av = *(const float4*)(A + (size_t)gi * N + j0 + cg * 4);
        float4 dj = *(const float4*)(g_dinv + j0 + cg * 4);
        v.x += di * dj.x * av.x;
        v.y += di * dj.y * av.y;
        v.z += di * dj.z * av.z;
        v.w += di * dj.w * av.w;
        *(float4*)(g_P + (size_t)gi * N + j0 + cg * 4) = v;
    }
}

// ===========================================================================
// Kernel 4: read-only row-sum of P -> e = rsqrt(rowsum)
// ===========================================================================
__global__ __launch_bounds__(256) void k_rowsum_P() {
    int row = blockIdx.x;
    const float4* p4 = (const float4*)(g_P + (size_t)row * N);
    float s = 0.f;
    for (int i = threadIdx.x; i < N / 4; i += 256) {
        float4 v = p4[i];
        s += v.x + v.y + v.z + v.w;
    }
    __shared__ float red[256];
    red[threadIdx.x] = s;
    __syncthreads();
    for (int o = 128; o > 0; o >>= 1) {
        if (threadIdx.x < o) red[threadIdx.x] += red[threadIdx.x + o];
        __syncthreads();
    }
    if (threadIdx.x == 0) g_e[row] = rsqrtf(red[0]);
}

// ===========================================================================
// Kernel 5: WARP-PER-ROW top-k + gather + linear (R14-proven).
// ===========================================================================
__global__ __launch_bounds__(256) void k_topk_out(const float* __restrict__ x,
                                                  const float* __restrict__ W,
                                                  const float* __restrict__ b,
                                                  const int* __restrict__ kp,
                                                  float* __restrict__ out) {
    __shared__ float Ws[64 * 65];      // Ws[f*65 + o] = W[o][f]
    __shared__ float selw[8][16];
    __shared__ int seliw[8][16];

    int tid = threadIdx.x, lane = tid & 31, wid = tid >> 5;
    int row = blockIdx.x * 8 + wid;

    for (int idx = tid; idx < 64 * 64; idx += 256) {
        int o = idx >> 6, f = idx & 63;
        Ws[f * 65 + o] = W[idx];
    }
    __syncthreads();

    int k = kp ? *kp : 4;
    if (k < 1) k = 1;
    if (k > 16) k = 16;

    const float* prow = g_P + (size_t)row * N;

    if (k <= 4) {
        float v0 = NEG_HUGE, v1 = NEG_HUGE, v2 = NEG_HUGE, v3 = NEG_HUGE;
        int i0 = N, i1 = N, i2 = N, i3 = N;
#pragma unroll
        for (int gq = 0; gq < 8; gq++) {
            float4 pv[4], ev[4];
#pragma unroll
            for (int q = 0; q < 4; q++) {
                int j = ((gq * 4 + q) * 32 + lane) * 4;
                pv[q] = *(const float4*)(prow + j);
                ev[q] = *(const float4*)(g_e + j);
            }
#pragma unroll
            for (int q = 0; q < 4; q++) {
                int j = ((gq * 4 + q) * 32 + lane) * 4;
                float vv[4] = {pv[q].x * ev[q].x, pv[q].y * ev[q].y,
                               pv[q].z * ev[q].z, pv[q].w * ev[q].w};
#pragma unroll
                for (int u = 0; u < 4; u++) {
                    float v = vv[u];
                    int idx = j + u;
                    if (v > v3) {
                        if (v > v0) {
                            v3 = v2; i3 = i2; v2 = v1; i2 = i1;
                            v1 = v0; i1 = i0; v0 = v; i0 = idx;
                        } else if (v > v1) {
                            v3 = v2; i3 = i2; v2 = v1; i2 = i1;
                            v1 = v; i1 = idx;
                        } else if (v > v2) {
                            v3 = v2; i3 = i2; v2 = v; i2 = idx;
                        } else {
                            v3 = v; i3 = idx;
                        }
                    }
                }
            }
        }
#pragma unroll
        for (int r = 0; r < 4; r++) {
            float bv = v0;
            int bi = i0;
#pragma unroll
            for (int o = 16; o > 0; o >>= 1) {
                float ov = __shfl_xor_sync(0xFFFFFFFF, bv, o);
                int oi = __shfl_xor_sync(0xFFFFFFFF, bi, o);
                if (ov > bv || (ov == bv && oi < bi)) { bv = ov; bi = oi; }
            }
            if (v0 == bv && i0 == bi) {
                v0 = v1; i0 = i1; v1 = v2; i1 = i2;
                v2 = v3; i2 = i3; v3 = NEG_HUGE; i3 = N;
            }
            if (lane == 0) { selw[wid][r] = bv; seliw[wid][r] = bi; }
        }
        __syncwarp();
    } else {
        float* vbuf = g_AtcP + (size_t)row * N;
        for (int j = lane; j < N; j += 32) vbuf[j] = g_e[j] * prow[j];
        __syncwarp();
        for (int s = 0; s < k; s++) {
            float bv = NEG_HUGE;
            int bi = N;
            for (int j = lane; j < N; j += 32) {
                float v = *(volatile float*)(vbuf + j);
                if (v > bv) { bv = v; bi = j; }
            }
#pragma unroll
            for (int o = 16; o > 0; o >>= 1) {
                float ov = __shfl_xor_sync(0xFFFFFFFF, bv, o);
                int oi = __shfl_xor_sync(0xFFFFFFFF, bi, o);
                if (ov > bv || (ov == bv && oi < bi)) { bv = ov; bi = oi; }
            }
            if (lane == 0) {
                selw[wid][s] = bv;
                seliw[wid][s] = bi;
                *(volatile float*)(vbuf + bi) = NEG_HUGE;
            }
            __syncwarp();
        }
    }

    float ei = g_e[row];
    float y0 = 0.f, y1 = 0.f;
    for (int s = 0; s < k; s++) {
        float w = ei * selw[wid][s];
        int idx = seliw[wid][s];
        y0 += w * x[(size_t)idx * DIN + lane];
        y1 += w * x[(size_t)idx * DIN + lane + 32];
    }
    float acc0 = b[lane], acc1 = b[lane + 32];
#pragma unroll
    for (int f = 0; f < 32; f++) {
        float yf = __shfl_sync(0xFFFFFFFF, y0, f);
        acc0 += yf * Ws[f * 65 + lane];
        acc1 += yf * Ws[f * 65 + lane + 32];
    }
#pragma unroll
    for (int f = 0; f < 32; f++) {
        float yf = __shfl_sync(0xFFFFFFFF, y1, f);
        acc0 += yf * Ws[(f + 32) * 65 + lane];
        acc1 += yf * Ws[(f + 32) * 65 + lane + 32];
    }
    out[(size_t)row * DOUT + lane] = acc0;
    out[(size_t)row * DOUT + lane + 32] = acc1;
}

// ===========================================================================
extern "C" void kernel_launch(void* const* d_in, const int* in_sizes, int n_in,
                              void* d_out, int out_size) {
    const float* x = (const float*)d_in[0];
    const float* A = (const float*)d_in[1];
    const float* theta = (const float*)d_in[2];
    const float* W = (const float*)d_in[3];
    const float* b = (const float*)d_in[4];
    const int* kp = (n_in > 5) ? (const int*)d_in[5] : nullptr;
    float* out = (float*)d_out;

    static bool attr_set = false;
    if (!attr_set) {
        cudaFuncSetAttribute(k_gemm_mma, cudaFuncAttributeMaxDynamicSharedMemorySize,
                             SMEM_BYTES);
        attr_set = true;
    }

    k_rowsum_A<<<N, 256>>>(A, theta);
    dim3 pb(32, 8);
    dim3 pg(N / 32, N / 32);
    k_prep<<<pg, pb>>>(A);
    k_nop<<<1, 32>>>();                    // keeps ncu capture on the GEMM
    dim3 gg(N / 128, N / 128);
    k_gemm_mma<<<gg, 256, SMEM_BYTES>>>(A);
    k_rowsum_P<<<N, 256>>>();
    k_topk_out<<<N / 8, 256>>>(x, W, b, kp, out);
}

// round 17
// speedup vs baseline: 1.7965x; 1.7965x over previous
#include <cuda_runtime.h>
#include <cstdint>
#include <math.h>

#define N 4096
#define DIN 64
#define DOUT 64
#define NEG_HUGE (-3.402823466e38f)

// ---- scratch (device globals; no runtime allocation) ----
__device__ __align__(16) float g_P[(size_t)N * N];     // 64 MB: final P
// A operand, [k][m'] with m-pairs (m, m+8) adjacent within 16-blocks
__device__ __align__(16) float g_AtcP[(size_t)N * N];  // also topk scratch later
// B operand, k-folded: phys row = (k>>3)*4 + (k&3), col = 2n + ((k>>2)&1)
__device__ __align__(16) float g_BtP[(size_t)N * N];   // (N/2) rows x 2N cols
__device__ __align__(16) float g_dinv[N];
__device__ __align__(16) float g_c[N];
__device__ __align__(16) float g_e[N];
__device__ __align__(16) float g_rowsum[N];            // accumulated in GEMM epilogue
__device__ float g_t[2];

// ===========================================================================
// helpers
// ===========================================================================
__device__ __forceinline__ uint32_t smem_u32(const void* p) {
    uint32_t a;
    asm("{ .reg .u64 t; cvta.to.shared.u64 t, %1; cvt.u32.u64 %0, t; }"
        : "=r"(a) : "l"(p));
    return a;
}
__device__ __forceinline__ float f2tf32(float x) {
    float y;
    asm("cvt.rna.tf32.f32 %0, %1;" : "=f"(y) : "f"(x));
    return y;
}
#define CP_ASYNC16(smem, gptr) \
    asm volatile("cp.async.cg.shared.global [%0], [%1], 16;" \
                 :: "r"(smem), "l"(gptr) : "memory")
#define CP_COMMIT() asm volatile("cp.async.commit_group;" ::: "memory")
#define CP_WAIT(n)  asm volatile("cp.async.wait_group %0;" :: "n"(n) : "memory")

__device__ __forceinline__ void mma_tf32(float* d, float2 a01, float2 a23,
                                         float2 b01) {
    asm volatile(
        "mma.sync.aligned.m16n8k8.row.col.f32.tf32.tf32.f32 "
        "{%0,%1,%2,%3}, {%4,%5,%6,%7}, {%8,%9}, {%0,%1,%2,%3};"
        : "+f"(d[0]), "+f"(d[1]), "+f"(d[2]), "+f"(d[3])
        : "r"(__float_as_uint(a01.x)), "r"(__float_as_uint(a01.y)),
          "r"(__float_as_uint(a23.x)), "r"(__float_as_uint(a23.y)),
          "r"(__float_as_uint(b01.x)), "r"(__float_as_uint(b01.y)));
}

// ===========================================================================
// Kernel 1: row sums of A -> dinv, c ; sigmoid(theta); zero g_rowsum
// ===========================================================================
__global__ __launch_bounds__(256) void k_rowsum_A(const float* __restrict__ A,
                                                  const float* __restrict__ theta) {
    int row = blockIdx.x;
    const float4* a4 = (const float4*)(A + (size_t)row * N);
    float s = 0.f;
    for (int i = threadIdx.x; i < N / 4; i += 256) {
        float4 v = a4[i];
        s += v.x + v.y + v.z + v.w;
    }
    __shared__ float red[256];
    red[threadIdx.x] = s;
    __syncthreads();
    for (int o = 128; o > 0; o >>= 1) {
        if (threadIdx.x < o) red[threadIdx.x] += red[threadIdx.x + o];
        __syncthreads();
    }
    if (threadIdx.x == 0) {
        float d = red[0];
        g_dinv[row] = rsqrtf(d);
        g_c[row] = 1.0f / d;
        g_rowsum[row] = 0.f;
        if (row == 0) {
            g_t[0] = 1.0f / (1.0f + expf(-theta[0]));
            g_t[1] = 1.0f / (1.0f + expf(-theta[1]));
        }
    }
}

// ===========================================================================
// Kernel 2: prep with pair-contiguous layouts (R9-proven).
// ===========================================================================
__global__ __launch_bounds__(256) void k_prep(const float* __restrict__ A) {
    __shared__ float ta[32][33];
    __shared__ float tb[32][33];
    int tx = threadIdx.x, ty = threadIdx.y;
    int x0 = blockIdx.x * 32, y0 = blockIdx.y * 32;
    float cc = g_c[x0 + tx];
#pragma unroll
    for (int r = 0; r < 4; r++) {
        int row = y0 + ty + r * 8;
        float v = A[(size_t)row * N + x0 + tx];
        tb[ty + r * 8][tx] = f2tf32(v);
        ta[ty + r * 8][tx] = f2tf32(v * cc);
    }
    __syncthreads();
#pragma unroll
    for (int rr = 0; rr < 2; rr++) {
        int p = ty + rr * 8;
        int i = 8 * (p >> 2) + (p & 3);
        float2 val = make_float2(tb[i][tx], tb[i + 4][tx]);
        *(float2*)(g_BtP + (size_t)(y0 / 2 + p) * (2 * N) + 2 * (x0 + tx)) = val;
    }
#pragma unroll
    for (int rr = 0; rr < 2; rr++) {
        int j = 2 * (ty + 8 * rr) + (tx >> 4);
        int q = tx & 15;
        int i = 16 * (q >> 3) + (q & 7);
        int col = y0 + 16 * (q >> 3) + 2 * (q & 7);
        float2 val = make_float2(ta[i][j], ta[i + 8][j]);
        *(float2*)(g_AtcP + (size_t)(x0 + j) * N + col) = val;
    }
}

// ===========================================================================
// dummy no-op: keeps ncu's captured launch index on the GEMM
// ===========================================================================
__global__ void k_nop() {}

// ===========================================================================
// Kernel 3: tf32 mma.sync GEMM — exact R14 structure (CTA 128x128, 8 warps
// 4m x 2n, warp 32x64, 2-stage cp.async, LDS.64 pair fragments, fused t0*A
// epilogue) + per-row partial sums accumulated to g_rowsum via RED.
//   g_P = dinv_i*dinv_j*(t0*A + t1*M) + I
// ===========================================================================
#define BK 32
#define NCH (N / BK)
#define PITCHA 136
#define PITCHB 264
#define TILEA_F (BK * PITCHA)
#define TILEB_F ((BK / 2) * PITCHB)
#define STAGE_F (TILEA_F + TILEB_F)
#define SMEM_BYTES (2 * STAGE_F * 4)

__device__ __forceinline__ void stage_chunk(uint32_t sbase, int buf, int ch,
                                            int i0, int j0, int tid) {
    int k0 = ch * BK;
    uint32_t sa = sbase + buf * (STAGE_F * 4);
    uint32_t sb = sa + TILEA_F * 4;
#pragma unroll
    for (int t = 0; t < 4; t++) {
        int id = tid + t * 256;
        int k = id >> 5, seg = id & 31;
        CP_ASYNC16(sa + k * (PITCHA * 4) + seg * 16,
                   g_AtcP + (size_t)(k0 + k) * N + i0 + seg * 4);
    }
#pragma unroll
    for (int t = 0; t < 4; t++) {
        int id = tid + t * 256;
        int r = id >> 6, seg = id & 63;
        CP_ASYNC16(sb + r * (PITCHB * 4) + seg * 16,
                   g_BtP + (size_t)(k0 / 2 + r) * (2 * N) + 2 * j0 + seg * 4);
    }
}

__global__ __launch_bounds__(256, 2) void k_gemm_mma(const float* __restrict__ A) {
    extern __shared__ float sm[];
    uint32_t sbase = smem_u32(sm);
    int tid = threadIdx.x;
    int wid = tid >> 5, lane = tid & 31;
    int g = lane >> 2, tig = lane & 3;
    int wm0 = (wid & 3) * 32, wn0 = (wid >> 2) * 64;
    int i0 = blockIdx.y * 128, j0 = blockIdx.x * 128;

    float acc[2][8][4];
#pragma unroll
    for (int mt = 0; mt < 2; mt++)
#pragma unroll
        for (int j = 0; j < 8; j++)
#pragma unroll
            for (int c = 0; c < 4; c++) acc[mt][j][c] = 0.f;

    stage_chunk(sbase, 0, 0, i0, j0, tid);
    CP_COMMIT();
    stage_chunk(sbase, 1, 1, i0, j0, tid);
    CP_COMMIT();

    for (int ch = 0; ch < NCH; ch++) {
        if (ch < NCH - 1) CP_WAIT(1);
        else              CP_WAIT(0);
        __syncthreads();

        const float* As = sm + (ch & 1) * STAGE_F;
        const float* Bs = As + TILEA_F;
#pragma unroll
        for (int s = 0; s < 4; s++) {
            float2 a01[2], a23[2];
#pragma unroll
            for (int mt = 0; mt < 2; mt++) {
                int col = wm0 + 16 * mt + 2 * g;
                a01[mt] = *(const float2*)(As + (8 * s + tig) * PITCHA + col);
                a23[mt] = *(const float2*)(As + (8 * s + tig + 4) * PITCHA + col);
            }
#pragma unroll
            for (int j = 0; j < 8; j++) {
                float2 b01 = *(const float2*)(Bs + (4 * s + tig) * PITCHB +
                                              2 * (wn0 + 8 * j + g));
                mma_tf32(acc[0][j], a01[0], a23[0], b01);
                mma_tf32(acc[1][j], a01[1], a23[1], b01);
            }
        }
        __syncthreads();
        if (ch + 2 < NCH) {
            stage_chunk(sbase, ch & 1, ch + 2, i0, j0, tid);
            CP_COMMIT();
        }
    }

    // ---- epilogue: t1*M scale + diag via smem transpose; t0*A term and
    //      per-row partial sums (RED to g_rowsum) in the coalesced store ----
    float t1 = g_t[1];
    float t0 = g_t[0];
    float* scr = sm;
#pragma unroll
    for (int mt = 0; mt < 2; mt++) {
        int m0 = wm0 + 16 * mt + g;
        int gi0 = i0 + m0, gi1 = gi0 + 8;
        float di0 = t1 * g_dinv[gi0];
        float di1 = t1 * g_dinv[gi1];
#pragma unroll
        for (int j = 0; j < 8; j++) {
            int n = wn0 + 8 * j + 2 * tig;
            int gj = j0 + n;
            float dj0 = g_dinv[gj], dj1 = g_dinv[gj + 1];
            float p00 = acc[mt][j][0] * di0 * dj0;
            float p01 = acc[mt][j][1] * di0 * dj1;
            float p10 = acc[mt][j][2] * di1 * dj0;
            float p11 = acc[mt][j][3] * di1 * dj1;
            if (gi0 == gj) p00 += 1.0f;
            if (gi0 == gj + 1) p01 += 1.0f;
            if (gi1 == gj) p10 += 1.0f;
            if (gi1 == gj + 1) p11 += 1.0f;
            *(float2*)(scr + m0 * 132 + n) = make_float2(p00, p01);
            *(float2*)(scr + (m0 + 8) * 132 + n) = make_float2(p10, p11);
        }
    }
    __syncthreads();
#pragma unroll
    for (int t = 0; t < 16; t++) {
        int id = tid + t * 256;
        int row = id >> 5, cg = id & 31;    // one warp == one full row segment
        int gi = i0 + row;
        float di = t0 * g_dinv[gi];
        float4 v = *(float4*)(scr + row * 132 + cg * 4);
        float4 av = *(const float4*)(A + (size_t)gi * N + j0 + cg * 4);
        float4 dj = *(const float4*)(g_dinv + j0 + cg * 4);
        v.x += di * dj.x * av.x;
        v.y += di * dj.y * av.y;
        v.z += di * dj.z * av.z;
        v.w += di * dj.w * av.w;
        *(float4*)(g_P + (size_t)gi * N + j0 + cg * 4) = v;
        // partial row sum: reduce this warp's 128-column segment
        float s4 = (v.x + v.y) + (v.z + v.w);
#pragma unroll
        for (int o = 16; o > 0; o >>= 1)
            s4 += __shfl_xor_sync(0xFFFFFFFF, s4, o);
        if (lane == 0) atomicAdd(g_rowsum + gi, s4);
    }
}

// ===========================================================================
// Kernel 4: tiny finalize — e = rsqrt(rowsum)
// ===========================================================================
__global__ __launch_bounds__(256) void k_e_fin() {
    int i = blockIdx.x * 256 + threadIdx.x;
    g_e[i] = rsqrtf(g_rowsum[i]);
}

// ===========================================================================
// Kernel 5: WARP-PER-ROW top-k + gather + linear (R14-proven).
// ===========================================================================
__global__ __launch_bounds__(256) void k_topk_out(const float* __restrict__ x,
                                                  const float* __restrict__ W,
                                                  const float* __restrict__ b,
                                                  const int* __restrict__ kp,
                                                  float* __restrict__ out) {
    __shared__ float Ws[64 * 65];      // Ws[f*65 + o] = W[o][f]
    __shared__ float selw[8][16];
    __shared__ int seliw[8][16];

    int tid = threadIdx.x, lane = tid & 31, wid = tid >> 5;
    int row = blockIdx.x * 8 + wid;

    for (int idx = tid; idx < 64 * 64; idx += 256) {
        int o = idx >> 6, f = idx & 63;
        Ws[f * 65 + o] = W[idx];
    }
    __syncthreads();

    int k = kp ? *kp : 4;
    if (k < 1) k = 1;
    if (k > 16) k = 16;

    const float* prow = g_P + (size_t)row * N;

    if (k <= 4) {
        float v0 = NEG_HUGE, v1 = NEG_HUGE, v2 = NEG_HUGE, v3 = NEG_HUGE;
        int i0 = N, i1 = N, i2 = N, i3 = N;
#pragma unroll
        for (int gq = 0; gq < 8; gq++) {
            float4 pv[4], ev[4];
#pragma unroll
            for (int q = 0; q < 4; q++) {
                int j = ((gq * 4 + q) * 32 + lane) * 4;
                pv[q] = *(const float4*)(prow + j);
                ev[q] = *(const float4*)(g_e + j);
            }
#pragma unroll
            for (int q = 0; q < 4; q++) {
                int j = ((gq * 4 + q) * 32 + lane) * 4;
                float vv[4] = {pv[q].x * ev[q].x, pv[q].y * ev[q].y,
                               pv[q].z * ev[q].z, pv[q].w * ev[q].w};
#pragma unroll
                for (int u = 0; u < 4; u++) {
                    float v = vv[u];
                    int idx = j + u;
                    if (v > v3) {
                        if (v > v0) {
                            v3 = v2; i3 = i2; v2 = v1; i2 = i1;
                            v1 = v0; i1 = i0; v0 = v; i0 = idx;
                        } else if (v > v1) {
                            v3 = v2; i3 = i2; v2 = v1; i2 = i1;
                            v1 = v; i1 = idx;
                        } else if (v > v2) {
                            v3 = v2; i3 = i2; v2 = v; i2 = idx;
                        } else {
                            v3 = v; i3 = idx;
                        }
                    }
                }
            }
        }
#pragma unroll
        for (int r = 0; r < 4; r++) {
            float bv = v0;
            int bi = i0;
#pragma unroll
            for (int o = 16; o > 0; o >>= 1) {
                float ov = __shfl_xor_sync(0xFFFFFFFF, bv, o);
                int oi = __shfl_xor_sync(0xFFFFFFFF, bi, o);
                if (ov > bv || (ov == bv && oi < bi)) { bv = ov; bi = oi; }
            }
            if (v0 == bv && i0 == bi) {
                v0 = v1; i0 = i1; v1 = v2; i1 = i2;
                v2 = v3; i2 = i3; v3 = NEG_HUGE; i3 = N;
            }
            if (lane == 0) { selw[wid][r] = bv; seliw[wid][r] = bi; }
        }
        __syncwarp();
    } else {
        float* vbuf = g_AtcP + (size_t)row * N;
        for (int j = lane; j < N; j += 32) vbuf[j] = g_e[j] * prow[j];
        __syncwarp();
        for (int s = 0; s < k; s++) {
            float bv = NEG_HUGE;
            int bi = N;
            for (int j = lane; j < N; j += 32) {
                float v = *(volatile float*)(vbuf + j);
                if (v > bv) { bv = v; bi = j; }
            }
#pragma unroll
            for (int o = 16; o > 0; o >>= 1) {
                float ov = __shfl_xor_sync(0xFFFFFFFF, bv, o);
                int oi = __shfl_xor_sync(0xFFFFFFFF, bi, o);
                if (ov > bv || (ov == bv && oi < bi)) { bv = ov; bi = oi; }
            }
            if (lane == 0) {
                selw[wid][s] = bv;
                seliw[wid][s] = bi;
                *(volatile float*)(vbuf + bi) = NEG_HUGE;
            }
            __syncwarp();
        }
    }

    float ei = g_e[row];
    float y0 = 0.f, y1 = 0.f;
    for (int s = 0; s < k; s++) {
        float w = ei * selw[wid][s];
        int idx = seliw[wid][s];
        y0 += w * x[(size_t)idx * DIN + lane];
        y1 += w * x[(size_t)idx * DIN + lane + 32];
    }
    float acc0 = b[lane], acc1 = b[lane + 32];
#pragma unroll
    for (int f = 0; f < 32; f++) {
        float yf = __shfl_sync(0xFFFFFFFF, y0, f);
        acc0 += yf * Ws[f * 65 + lane];
        acc1 += yf * Ws[f * 65 + lane + 32];
    }
#pragma unroll
    for (int f = 0; f < 32; f++) {
        float yf = __shfl_sync(0xFFFFFFFF, y1, f);
        acc0 += yf * Ws[(f + 32) * 65 + lane];
        acc1 += yf * Ws[(f + 32) * 65 + lane + 32];
    }
    out[(size_t)row * DOUT + lane] = acc0;
    out[(size_t)row * DOUT + lane + 32] = acc1;
}

// ===========================================================================
extern "C" void kernel_launch(void* const* d_in, const int* in_sizes, int n_in,
                              void* d_out, int out_size) {
    const float* x = (const float*)d_in[0];
    const float* A = (const float*)d_in[1];
    const float* theta = (const float*)d_in[2];
    const float* W = (const float*)d_in[3];
    const float* b = (const float*)d_in[4];
    const int* kp = (n_in > 5) ? (const int*)d_in[5] : nullptr;
    float* out = (float*)d_out;

    static bool attr_set = false;
    if (!attr_set) {
        cudaFuncSetAttribute(k_gemm_mma, cudaFuncAttributeMaxDynamicSharedMemorySize,
                             SMEM_BYTES);
        attr_set = true;
    }

    k_rowsum_A<<<N, 256>>>(A, theta);
    dim3 pb(32, 8);
    dim3 pg(N / 32, N / 32);
    k_prep<<<pg, pb>>>(A);
    k_nop<<<1, 32>>>();                    // keeps ncu capture on the GEMM
    dim3 gg(N / 128, N / 128);
    k_gemm_mma<<<gg, 256, SMEM_BYTES>>>(A);
    k_e_fin<<<N / 256, 256>>>();
    k_topk_out<<<N / 8, 256>>>(x, W, b, kp, out);
}